// round 3
// baseline (speedup 1.0000x reference)
#include <cuda_runtime.h>

#define BB 8192
#define TT 140
#define HH 64
#define ROWS 64
#define THREADS 256
#define NW 8
#define HS 68   // h row stride in floats: stride 272B -> conflict-free float4 ld/st

typedef unsigned long long ull;

struct __align__(16) Smem {
    float2 w0[64][32];       // W_hh0 packed: [k][jp] = (W[2jp][k], W[2jp+1][k])
    float2 w1i[64][32];      // W_ih1 packed
    float2 w1h[64][32];      // W_hh1 packed
    float  h0[2][ROWS][HS];  // double-buffered
    float  h1[2][ROWS][HS];
    float2 wih0p[32];
    float2 b0p[32];
    float2 b1p[32];
    float  wout[64];
    float  ypart[2][NW][ROWS];
};

__device__ __forceinline__ ull pack2(float lo, float hi) {
    ull r;
    asm("mov.b64 %0, {%1, %2};" : "=l"(r) : "f"(lo), "f"(hi));
    return r;
}
__device__ __forceinline__ void unpack2(ull v, float& lo, float& hi) {
    asm("mov.b64 {%0, %1}, %2;" : "=f"(lo), "=f"(hi) : "l"(v));
}
__device__ __forceinline__ ull fma2(ull a, ull b, ull c) {
    ull d;
    asm("fma.rn.f32x2 %0, %1, %2, %3;" : "=l"(d) : "l"(a), "l"(b), "l"(c));
    return d;
}
__device__ __forceinline__ float fast_tanh(float x) {
    float e = __expf(2.0f * x);
    return 1.0f - __fdividef(2.0f, e + 1.0f);
}

// acc[0..3] (+= row0), acc[4..7] (+= row1): 4 jp columns each, k = 0..63
__device__ __forceinline__ void matvec2(ull (&acc)[8],
                                        const float2 (&W)[64][32],
                                        const float* __restrict__ hr0,
                                        const float* __restrict__ hr1, int jp0) {
    const char* wb = reinterpret_cast<const char*>(&W[0][jp0]);
#pragma unroll 4
    for (int k4 = 0; k4 < 64; k4 += 4) {
        float4 a = *reinterpret_cast<const float4*>(hr0 + k4);
        float4 b = *reinterpret_cast<const float4*>(hr1 + k4);
        ull ap[4], bp[4];
        ap[0] = pack2(a.x, a.x); ap[1] = pack2(a.y, a.y);
        ap[2] = pack2(a.z, a.z); ap[3] = pack2(a.w, a.w);
        bp[0] = pack2(b.x, b.x); bp[1] = pack2(b.y, b.y);
        bp[2] = pack2(b.z, b.z); bp[3] = pack2(b.w, b.w);
#pragma unroll
        for (int kk = 0; kk < 4; ++kk) {
            const ulonglong2* wk =
                reinterpret_cast<const ulonglong2*>(wb + (k4 + kk) * 256);
            ulonglong2 wA = wk[0], wB = wk[1];
            acc[0] = fma2(ap[kk], wA.x, acc[0]);
            acc[1] = fma2(ap[kk], wA.y, acc[1]);
            acc[2] = fma2(ap[kk], wB.x, acc[2]);
            acc[3] = fma2(ap[kk], wB.y, acc[3]);
            acc[4] = fma2(bp[kk], wA.x, acc[4]);
            acc[5] = fma2(bp[kk], wA.y, acc[5]);
            acc[6] = fma2(bp[kk], wB.x, acc[6]);
            acc[7] = fma2(bp[kk], wB.y, acc[7]);
        }
    }
}

__global__ void __launch_bounds__(THREADS, 1) rnn_kernel(
    const float* __restrict__ x, const float* __restrict__ h_state,
    const float* __restrict__ Wih0, const float* __restrict__ Whh0,
    const float* __restrict__ bih0, const float* __restrict__ bhh0,
    const float* __restrict__ Wih1, const float* __restrict__ Whh1,
    const float* __restrict__ bih1, const float* __restrict__ bhh1,
    const float* __restrict__ Wout, const float* __restrict__ bout,
    float* __restrict__ out) {
    extern __shared__ char smraw[];
    Smem* sm = reinterpret_cast<Smem*>(smraw);
    const int tid  = threadIdx.x;
    const int lane = tid & 31;
    const int w    = tid >> 5;
    const int jp0  = w * 4;       // 4 jp columns (8 j values) per warp
    const int row0 = blockIdx.x * ROWS;

    // ---- prologue ----
    for (int i = tid; i < 2048; i += THREADS) {
        int k = i >> 5, jp = i & 31;
        sm->w0[k][jp]  = make_float2(Whh0[(2 * jp) * HH + k], Whh0[(2 * jp + 1) * HH + k]);
        sm->w1i[k][jp] = make_float2(Wih1[(2 * jp) * HH + k], Wih1[(2 * jp + 1) * HH + k]);
        sm->w1h[k][jp] = make_float2(Whh1[(2 * jp) * HH + k], Whh1[(2 * jp + 1) * HH + k]);
    }
    for (int i = tid; i < ROWS * HH; i += THREADS) {
        int r = i >> 6, k = i & 63;
        sm->h0[0][r][k] = h_state[(row0 + r) * HH + k];
        sm->h1[0][r][k] = h_state[(BB + row0 + r) * HH + k];
    }
    if (tid < 32) {
        int jp = tid;
        sm->wih0p[jp] = make_float2(Wih0[2 * jp], Wih0[2 * jp + 1]);
        sm->b0p[jp] = make_float2(bih0[2 * jp] + bhh0[2 * jp],
                                  bih0[2 * jp + 1] + bhh0[2 * jp + 1]);
        sm->b1p[jp] = make_float2(bih1[2 * jp] + bhh1[2 * jp],
                                  bih1[2 * jp + 1] + bhh1[2 * jp + 1]);
        sm->wout[2 * jp]     = Wout[2 * jp];
        sm->wout[2 * jp + 1] = Wout[2 * jp + 1];
    }
    const float bo = bout[0];
    const float* gx0 = x + (row0 + lane) * TT;
    const float* gx1 = gx0 + 32 * TT;
    float xv0 = gx0[0], xv1 = gx1[0];
    __syncthreads();

    // ---- hoist per-warp constants into registers ----
    ull wiR[4], b0R[4], b1R[4];
    float woR[8];
    {
        const ull* wi  = reinterpret_cast<const ull*>(sm->wih0p);
        const ull* bb0 = reinterpret_cast<const ull*>(sm->b0p);
        const ull* bb1 = reinterpret_cast<const ull*>(sm->b1p);
#pragma unroll
        for (int i = 0; i < 4; ++i) {
            wiR[i] = wi[jp0 + i];
            b0R[i] = bb0[jp0 + i];
            b1R[i] = bb1[jp0 + i];
        }
#pragma unroll
        for (int i = 0; i < 8; ++i) woR[i] = sm->wout[8 * w + i];
    }

    int p = 0, q = 0;
    // ---- recurrence: ONE barrier per step ----
    for (int t = 0; t < TT; ++t) {
        float xc0 = xv0, xc1 = xv1;
        int tn = (t + 1 < TT) ? t + 1 : TT - 1;
        xv0 = gx0[tn]; xv1 = gx1[tn];  // prefetch next step's x

        // layer 0
        ull acc[8];
        {
            ull xp0 = pack2(xc0, xc0), xp1 = pack2(xc1, xc1);
#pragma unroll
            for (int i = 0; i < 4; ++i) {
                acc[i]     = fma2(xp0, wiR[i], b0R[i]);
                acc[4 + i] = fma2(xp1, wiR[i], b0R[i]);
            }
        }
        matvec2(acc, sm->w0, sm->h0[p][lane], sm->h0[p][lane + 32], jp0);
        float hv0[8], hv1[8];
#pragma unroll
        for (int i = 0; i < 4; ++i) {
            float lo, hi;
            unpack2(acc[i], lo, hi);
            hv0[2 * i] = fast_tanh(lo); hv0[2 * i + 1] = fast_tanh(hi);
            unpack2(acc[4 + i], lo, hi);
            hv1[2 * i] = fast_tanh(lo); hv1[2 * i + 1] = fast_tanh(hi);
        }
        const int pn = p ^ 1;
        *reinterpret_cast<float4*>(&sm->h0[pn][lane][8 * w]) =
            make_float4(hv0[0], hv0[1], hv0[2], hv0[3]);
        *reinterpret_cast<float4*>(&sm->h0[pn][lane][8 * w + 4]) =
            make_float4(hv0[4], hv0[5], hv0[6], hv0[7]);
        *reinterpret_cast<float4*>(&sm->h0[pn][lane + 32][8 * w]) =
            make_float4(hv1[0], hv1[1], hv1[2], hv1[3]);
        *reinterpret_cast<float4*>(&sm->h0[pn][lane + 32][8 * w + 4]) =
            make_float4(hv1[4], hv1[5], hv1[6], hv1[7]);
        __syncthreads();  // the only barrier per step

        // delayed y-reduce for step t-1
        if (t > 0 && w < 2) {
            int r = w * 32 + lane;
            float yv = bo;
#pragma unroll
            for (int i = 0; i < NW; ++i) yv += sm->ypart[q ^ 1][i][r];
            out[(row0 + r) * TT + (t - 1)] = yv;
        }

        // layer 1
#pragma unroll
        for (int i = 0; i < 4; ++i) { acc[i] = b1R[i]; acc[4 + i] = b1R[i]; }
        matvec2(acc, sm->w1i, sm->h0[pn][lane], sm->h0[pn][lane + 32], jp0);
        matvec2(acc, sm->w1h, sm->h1[p][lane], sm->h1[p][lane + 32], jp0);
        float yp0 = 0.0f, yp1 = 0.0f;
#pragma unroll
        for (int i = 0; i < 4; ++i) {
            float lo, hi;
            unpack2(acc[i], lo, hi);
            lo = fast_tanh(lo); hi = fast_tanh(hi);
            hv0[2 * i] = lo; hv0[2 * i + 1] = hi;
            yp0 += lo * woR[2 * i] + hi * woR[2 * i + 1];
            unpack2(acc[4 + i], lo, hi);
            lo = fast_tanh(lo); hi = fast_tanh(hi);
            hv1[2 * i] = lo; hv1[2 * i + 1] = hi;
            yp1 += lo * woR[2 * i] + hi * woR[2 * i + 1];
        }
        *reinterpret_cast<float4*>(&sm->h1[pn][lane][8 * w]) =
            make_float4(hv0[0], hv0[1], hv0[2], hv0[3]);
        *reinterpret_cast<float4*>(&sm->h1[pn][lane][8 * w + 4]) =
            make_float4(hv0[4], hv0[5], hv0[6], hv0[7]);
        *reinterpret_cast<float4*>(&sm->h1[pn][lane + 32][8 * w]) =
            make_float4(hv1[0], hv1[1], hv1[2], hv1[3]);
        *reinterpret_cast<float4*>(&sm->h1[pn][lane + 32][8 * w + 4]) =
            make_float4(hv1[4], hv1[5], hv1[6], hv1[7]);
        sm->ypart[q][w][lane]      = yp0;
        sm->ypart[q][w][lane + 32] = yp1;
        p = pn; q ^= 1;
    }
    __syncthreads();

    // final y (t = TT-1)
    if (w < 2) {
        int r = w * 32 + lane;
        float yv = bo;
#pragma unroll
        for (int i = 0; i < NW; ++i) yv += sm->ypart[q ^ 1][i][r];
        out[(row0 + r) * TT + (TT - 1)] = yv;
    }
    // h_final
    const int BT = BB * TT;
    for (int i = tid; i < ROWS * HH; i += THREADS) {
        int r = i >> 6, k = i & 63;
        out[BT + (row0 + r) * HH + k]           = sm->h0[p][r][k];
        out[BT + BB * HH + (row0 + r) * HH + k] = sm->h1[p][r][k];
    }
}

extern "C" void kernel_launch(void* const* d_in, const int* in_sizes, int n_in,
                              void* d_out, int out_size) {
    (void)in_sizes; (void)n_in; (void)out_size;
    const float* x    = (const float*)d_in[0];
    const float* hs   = (const float*)d_in[1];
    const float* Wih0 = (const float*)d_in[2];
    const float* Whh0 = (const float*)d_in[3];
    const float* bih0 = (const float*)d_in[4];
    const float* bhh0 = (const float*)d_in[5];
    const float* Wih1 = (const float*)d_in[6];
    const float* Whh1 = (const float*)d_in[7];
    const float* bih1 = (const float*)d_in[8];
    const float* bhh1 = (const float*)d_in[9];
    const float* Wout = (const float*)d_in[10];
    const float* bout = (const float*)d_in[11];
    float* out = (float*)d_out;

    cudaFuncSetAttribute(rnn_kernel, cudaFuncAttributeMaxDynamicSharedMemorySize,
                         (int)sizeof(Smem));
    rnn_kernel<<<BB / ROWS, THREADS, sizeof(Smem)>>>(
        x, hs, Wih0, Whh0, bih0, bhh0, Wih1, Whh1, bih1, bhh1, Wout, bout, out);
}

// round 4
// speedup vs baseline: 1.0252x; 1.0252x over previous
#include <cuda_runtime.h>

#define BB 8192
#define TT 140
#define ROWS 64
#define THREADS 256
#define HSTR 76            // h row stride (floats); 304B, 16B-aligned, bank-spread

// smem float offsets
#define OFF_W   0                  // 3 * 4096 floats (48KB)
#define OFF_H0  12288              // 64*76
#define OFF_H1  (12288 + 4864)
#define OFF_XT  (12288 + 2*4864)   // 140*64
#define SMEM_FLOATS (OFF_XT + TT*64)

typedef unsigned long long ull;

__device__ __forceinline__ ull fma2(ull a, ull b, ull c) {
    ull d;
    asm("fma.rn.f32x2 %0, %1, %2, %3;" : "=l"(d) : "l"(a), "l"(b), "l"(c));
    return d;
}
__device__ __forceinline__ float foldadd(ull v) {   // lo + hi
    float lo, hi;
    asm("mov.b64 {%0, %1}, %2;" : "=f"(lo), "=f"(hi) : "l"(v));
    return lo + hi;
}
__device__ __forceinline__ float fast_tanh(float x) {
    float e = __expf(2.0f * x);
    return 1.0f - __fdividef(2.0f, e + 1.0f);
}

// acc[rr][i] += sum_k h_rr[k] * W[j=jg*8+i][k], split even/odd-k across f32x2 halves
#define MVEC(acc, wb, hA, hB)                                                   \
    _Pragma("unroll")                                                           \
    for (int k4 = 0; k4 < 16; ++k4) {                                           \
        ulonglong2 hva = *reinterpret_cast<const ulonglong2*>((hA) + k4 * 4);   \
        ulonglong2 hvb = *reinterpret_cast<const ulonglong2*>((hB) + k4 * 4);   \
        _Pragma("unroll")                                                       \
        for (int i = 0; i < 8; ++i) {                                           \
            ulonglong2 wv = *reinterpret_cast<const ulonglong2*>(                \
                (wb) + k4 * 1024 + i * 128);                                    \
            acc[0][i] = fma2(hva.x, wv.x, acc[0][i]);                           \
            acc[0][i] = fma2(hva.y, wv.y, acc[0][i]);                           \
            acc[1][i] = fma2(hvb.x, wv.x, acc[1][i]);                           \
            acc[1][i] = fma2(hvb.y, wv.y, acc[1][i]);                           \
        }                                                                       \
    }

__global__ void __launch_bounds__(THREADS, 1) rnn_kernel(
    const float* __restrict__ x, const float* __restrict__ h_state,
    const float* __restrict__ Wih0, const float* __restrict__ Whh0,
    const float* __restrict__ bih0, const float* __restrict__ bhh0,
    const float* __restrict__ Wih1, const float* __restrict__ Whh1,
    const float* __restrict__ bih1, const float* __restrict__ bhh1,
    const float* __restrict__ Wout, const float* __restrict__ bout,
    float* __restrict__ out) {
    extern __shared__ float smem[];
    const int tid  = threadIdx.x;
    const int lane = tid & 31;
    const int w    = tid >> 5;
    const int rg   = lane & 3;
    const int jg   = lane >> 2;
    const int row0 = blockIdx.x * ROWS;

    // ---- prologue: weights into [k4][i][jg] float4 layout ----
    {
        const float* Ws[3] = {Whh0, Wih1, Whh1};
#pragma unroll
        for (int m = 0; m < 3; ++m) {
            const float4* G = reinterpret_cast<const float4*>(Ws[m]);
            for (int idx = tid; idx < 1024; idx += THREADS) {
                int k4 = idx & 15, jrow = idx >> 4;      // jrow = j
                int ii = jrow & 7, jgg = jrow >> 3;
                float4 v = G[jrow * 16 + k4];            // W[j][4k4..4k4+3]
                *reinterpret_cast<float4*>(
                    &smem[OFF_W + m * 4096 + k4 * 256 + ii * 32 + jgg * 4]) = v;
            }
        }
    }
    // x transposed: xT[t][r]
    for (int idx = tid; idx < ROWS * TT; idx += THREADS) {
        int r = idx / TT, t = idx - r * TT;
        smem[OFF_XT + t * 64 + r] = x[(row0 + r) * TT + t];
    }
    // h state
    for (int idx = tid; idx < ROWS * 64; idx += THREADS) {
        int r = idx >> 6, k = idx & 63;
        smem[OFF_H0 + r * HSTR + k] = h_state[(row0 + r) * 64 + k];
        smem[OFF_H1 + r * HSTR + k] = h_state[(BB + row0 + r) * 64 + k];
    }
    // per-lane constants (j = jg*8 + i)
    float wiC[8], b0C[8], b1C[8], woC[8];
#pragma unroll
    for (int i = 0; i < 8; ++i) {
        int j = jg * 8 + i;
        wiC[i] = Wih0[j];
        b0C[i] = bih0[j] + bhh0[j];
        b1C[i] = bih1[j] + bhh1[j];
        woC[i] = Wout[j];
    }
    const float bo = bout[0];
    __syncthreads();

    // ---- per-lane pointers (all hot-loop offsets are immediates) ----
    const char* wp0 = reinterpret_cast<const char*>(&smem[OFF_W])         + jg * 16;
    const char* wp1 = reinterpret_cast<const char*>(&smem[OFF_W + 4096])  + jg * 16;
    const char* wp2 = reinterpret_cast<const char*>(&smem[OFF_W + 8192])  + jg * 16;
    const int r0 = w * 8 + 2 * rg;                    // this lane's 2 rows
    const float* h0a = &smem[OFF_H0 + r0 * HSTR];
    const float* h0b = h0a + HSTR;
    const float* h1a = &smem[OFF_H1 + r0 * HSTR];
    const float* h1b = h1a + HSTR;
    float* s0a = &smem[OFF_H0 + r0 * HSTR + jg * 8];  // store slots (j range)
    float* s0b = s0a + HSTR;
    float* s1a = &smem[OFF_H1 + r0 * HSTR + jg * 8];
    float* s1b = s1a + HSTR;
    const float* xtp = &smem[OFF_XT + w * 8 + 2 * rg];
    float* outp = out + (row0 + r0) * TT;             // rows r0, r0+1

    const ull z = 0;
    // ---- recurrence: NO block-level barrier ----
    for (int t = 0; t < TT; ++t) {
        // layer 0: h0n = tanh(x*wi + b + Whh0 h0)
        ull acc[2][8];
#pragma unroll
        for (int i = 0; i < 8; ++i) { acc[0][i] = z; acc[1][i] = z; }
        MVEC(acc, wp0, h0a, h0b);
        float xa = xtp[t * 64], xb = xtp[t * 64 + 1];
        float ha[8], hb[8];
#pragma unroll
        for (int i = 0; i < 8; ++i) {
            float base = fmaf(xa, wiC[i], b0C[i]);
            ha[i] = fast_tanh(foldadd(acc[0][i]) + base);
            float base2 = fmaf(xb, wiC[i], b0C[i]);
            hb[i] = fast_tanh(foldadd(acc[1][i]) + base2);
        }
        __syncwarp();   // all lanes finished reading h0(t-1)
        *reinterpret_cast<float4*>(s0a)     = make_float4(ha[0], ha[1], ha[2], ha[3]);
        *reinterpret_cast<float4*>(s0a + 4) = make_float4(ha[4], ha[5], ha[6], ha[7]);
        *reinterpret_cast<float4*>(s0b)     = make_float4(hb[0], hb[1], hb[2], hb[3]);
        *reinterpret_cast<float4*>(s0b + 4) = make_float4(hb[4], hb[5], hb[6], hb[7]);
        __syncwarp();   // h0n visible to warp

        // layer 1: h1n = tanh(Wih1 h0n + b + Whh1 h1)
#pragma unroll
        for (int i = 0; i < 8; ++i) { acc[0][i] = z; acc[1][i] = z; }
        MVEC(acc, wp1, h0a, h0b);
        MVEC(acc, wp2, h1a, h1b);
        float ya = 0.0f, yb = 0.0f;
#pragma unroll
        for (int i = 0; i < 8; ++i) {
            float va = fast_tanh(foldadd(acc[0][i]) + b1C[i]);
            float vb = fast_tanh(foldadd(acc[1][i]) + b1C[i]);
            ha[i] = va; hb[i] = vb;
            ya = fmaf(va, woC[i], ya);
            yb = fmaf(vb, woC[i], yb);
        }
        __syncwarp();   // all lanes finished reading h1(t-1)
        *reinterpret_cast<float4*>(s1a)     = make_float4(ha[0], ha[1], ha[2], ha[3]);
        *reinterpret_cast<float4*>(s1a + 4) = make_float4(ha[4], ha[5], ha[6], ha[7]);
        *reinterpret_cast<float4*>(s1b)     = make_float4(hb[0], hb[1], hb[2], hb[3]);
        *reinterpret_cast<float4*>(s1b + 4) = make_float4(hb[4], hb[5], hb[6], hb[7]);

        // y reduce across jg (bits 2..4), rg (rows) preserved
        ya += __shfl_xor_sync(0xFFFFFFFF, ya, 4);
        ya += __shfl_xor_sync(0xFFFFFFFF, ya, 8);
        ya += __shfl_xor_sync(0xFFFFFFFF, ya, 16);
        yb += __shfl_xor_sync(0xFFFFFFFF, yb, 4);
        yb += __shfl_xor_sync(0xFFFFFFFF, yb, 8);
        yb += __shfl_xor_sync(0xFFFFFFFF, yb, 16);
        if (jg == 0) {
            outp[t]      = ya + bo;
            outp[TT + t] = yb + bo;
        }
        __syncwarp();   // h1n visible before next step
    }
    __syncthreads();

    // ---- epilogue: h_final ----
    const int BT = BB * TT;
    for (int idx = tid; idx < ROWS * 64; idx += THREADS) {
        int r = idx >> 6, k = idx & 63;
        out[BT + (row0 + r) * 64 + k]           = smem[OFF_H0 + r * HSTR + k];
        out[BT + BB * 64 + (row0 + r) * 64 + k] = smem[OFF_H1 + r * HSTR + k];
    }
}

extern "C" void kernel_launch(void* const* d_in, const int* in_sizes, int n_in,
                              void* d_out, int out_size) {
    (void)in_sizes; (void)n_in; (void)out_size;
    const float* x    = (const float*)d_in[0];
    const float* hs   = (const float*)d_in[1];
    const float* Wih0 = (const float*)d_in[2];
    const float* Whh0 = (const float*)d_in[3];
    const float* bih0 = (const float*)d_in[4];
    const float* bhh0 = (const float*)d_in[5];
    const float* Wih1 = (const float*)d_in[6];
    const float* Whh1 = (const float*)d_in[7];
    const float* bih1 = (const float*)d_in[8];
    const float* bhh1 = (const float*)d_in[9];
    const float* Wout = (const float*)d_in[10];
    const float* bout = (const float*)d_in[11];
    float* out = (float*)d_out;

    size_t smem_bytes = SMEM_FLOATS * sizeof(float);
    cudaFuncSetAttribute(rnn_kernel, cudaFuncAttributeMaxDynamicSharedMemorySize,
                         (int)smem_bytes);
    rnn_kernel<<<BB / ROWS, THREADS, smem_bytes>>>(
        x, hs, Wih0, Whh0, bih0, bhh0, Wih1, Whh1, bih1, bhh1, Wout, bout, out);
}

// round 6
// speedup vs baseline: 2.5748x; 2.5115x over previous
#include <cuda_runtime.h>
#include <cuda_bf16.h>

typedef unsigned int u32;

#define BB 8192
#define TT 140
#define MROWS 64
#define THREADS 128

// smem byte offsets
// weights: 6 terms x 8192B: 0:W0hi 1:W0lo 2:W1ihi 3:W1ilo 4:W1hhi 5:W1hlo
#define OFF_W    0
#define OFF_H    49152          // 4 bufs x 8192B: h0hi,h0lo,h1hi,h1lo
#define OFF_XT   81920          // xT[t][r] 140*64 floats
#define SMEM_BYTES (OFF_XT + TT*64*4)

__device__ __forceinline__ u32 s2u(const void* p) {
    u32 a;
    asm("{ .reg .u64 t; cvta.to.shared.u64 t, %1; cvt.u32.u64 %0, t; }"
        : "=r"(a) : "l"(p));
    return a;
}
#define LDSM4(r0, r1, r2, r3, a)                                          \
    asm volatile("ldmatrix.sync.aligned.m8n8.x4.shared.b16 "              \
                 "{%0,%1,%2,%3}, [%4];"                                   \
                 : "=r"(r0), "=r"(r1), "=r"(r2), "=r"(r3) : "r"(a))

__device__ __forceinline__ void mma16816(float (&d)[4], u32 a0, u32 a1,
                                         u32 a2, u32 a3, u32 b0, u32 b1) {
    asm volatile(
        "mma.sync.aligned.m16n8k16.row.col.f32.bf16.bf16.f32 "
        "{%0,%1,%2,%3}, {%4,%5,%6,%7}, {%8,%9}, {%0,%1,%2,%3};"
        : "+f"(d[0]), "+f"(d[1]), "+f"(d[2]), "+f"(d[3])
        : "r"(a0), "r"(a1), "r"(a2), "r"(a3), "r"(b0), "r"(b1));
}
__device__ __forceinline__ u32 cvtpack(float hi, float lo) {  // {lo, hi} bf16x2
    u32 r;
    asm("cvt.rn.bf16x2.f32 %0, %1, %2;" : "=r"(r) : "f"(hi), "f"(lo));
    return r;
}
__device__ __forceinline__ float fast_tanh(float x) {
    float e = __expf(2.0f * x);
    return 1.0f - __fdividef(2.0f, e + 1.0f);
}

__global__ void __launch_bounds__(THREADS, 1) rnn_kernel(
    const float* __restrict__ x, const float* __restrict__ h_state,
    const float* __restrict__ Wih0, const float* __restrict__ Whh0,
    const float* __restrict__ bih0, const float* __restrict__ bhh0,
    const float* __restrict__ Wih1, const float* __restrict__ Whh1,
    const float* __restrict__ bih1, const float* __restrict__ bhh1,
    const float* __restrict__ Wout, const float* __restrict__ bout,
    float* __restrict__ out) {
    extern __shared__ char smem[];
    const int tid  = threadIdx.x;
    const int lane = tid & 31;
    const int w    = tid >> 5;
    const int g    = lane >> 2;     // row group 0..7
    const int tg   = lane & 3;      // col group 0..3
    const int wr0  = w * 16;        // warp's first CTA-local row
    const int row0 = blockIdx.x * MROWS;

    // ---- prologue: weights -> bf16 hi/lo, SW128-swizzled [j][k] ----
    {
        const float* Ws[3] = {Whh0, Wih1, Whh1};
        for (int idx = tid; idx < 3 * 4096; idx += THREADS) {
            int m = idx >> 12, e = idx & 4095, j = e >> 6, k = e & 63;
            float v = Ws[m][j * 64 + k];
            __nv_bfloat16 hb = __float2bfloat16(v);
            __nv_bfloat16 lb = __float2bfloat16(v - __bfloat162float(hb));
            int sw = j * 128 + ((k * 2) ^ ((j & 7) << 4));
            *(__nv_bfloat16*)(smem + OFF_W + (2 * m) * 8192 + sw)     = hb;
            *(__nv_bfloat16*)(smem + OFF_W + (2 * m + 1) * 8192 + sw) = lb;
        }
    }
    // h_state -> 4 bufs
    for (int idx = tid; idx < MROWS * 64; idx += THREADS) {
        int r = idx >> 6, k = idx & 63;
        int sw = r * 128 + ((k * 2) ^ ((r & 7) << 4));
        float v0 = h_state[(row0 + r) * 64 + k];
        float v1 = h_state[BB * 64 + (row0 + r) * 64 + k];
        __nv_bfloat16 h0h = __float2bfloat16(v0);
        __nv_bfloat16 h1h = __float2bfloat16(v1);
        *(__nv_bfloat16*)(smem + OFF_H + sw)         = h0h;
        *(__nv_bfloat16*)(smem + OFF_H + 8192 + sw)  = __float2bfloat16(v0 - __bfloat162float(h0h));
        *(__nv_bfloat16*)(smem + OFF_H + 16384 + sw) = h1h;
        *(__nv_bfloat16*)(smem + OFF_H + 24576 + sw) = __float2bfloat16(v1 - __bfloat162float(h1h));
    }
    // xT[t][r]
    {
        float* xTw = (float*)(smem + OFF_XT);
        for (int idx = tid; idx < MROWS * TT; idx += THREADS) {
            int r = idx / TT, t = idx - r * TT;
            xTw[t * 64 + r] = x[(row0 + r) * TT + t];
        }
    }
    // per-lane constants: cols j = nt*8 + tg*2, +1
    float2 wi2[8], b02[8], b12[8], wo2[8];
#pragma unroll
    for (int nt = 0; nt < 8; ++nt) {
        int j = nt * 8 + tg * 2;
        wi2[nt] = make_float2(Wih0[j], Wih0[j + 1]);
        b02[nt] = make_float2(bih0[j] + bhh0[j], bih0[j + 1] + bhh0[j + 1]);
        b12[nt] = make_float2(bih1[j] + bhh1[j], bih1[j + 1] + bhh1[j + 1]);
        wo2[nt] = make_float2(Wout[j], Wout[j + 1]);
    }
    const float bo = bout[0];
    __syncthreads();

    const u32 smu = s2u(smem);
    const int q    = lane >> 3;
    const int arow = wr0 + ((q & 1) << 3) + (lane & 7);
    const u32 aco  = (u32)((q >> 1) << 4);
    const u32 swz  = (u32)((lane & 7) << 4);
    const u32 abase = smu + OFF_H + arow * 128;
    const int brl  = (((lane >> 4) & 1) << 3) + (lane & 7);
    const u32 bco  = (u32)(((lane >> 3) & 1) << 4);
    const u32 bbase = smu + OFF_W + brl * 128;
    u32 stA[8], stB[8];
#pragma unroll
    for (int nt = 0; nt < 8; ++nt) {
        u32 c = (u32)((nt * 16 + tg * 4) ^ (g << 4));
        stA[nt] = smu + OFF_H + (wr0 + g) * 128 + c;
        stB[nt] = stA[nt] + 8 * 128;
    }
    const float* xT = (const float*)(smem + OFF_XT);
    float* outy = out + (row0 + wr0 + g) * TT;

    for (int t = 0; t < TT; ++t) {
        float xA = xT[t * 64 + wr0 + g];
        float xB = xT[t * 64 + wr0 + g + 8];

        // ================= layer 0 =================
        float acc[8][4];
#pragma unroll
        for (int n = 0; n < 8; ++n)
#pragma unroll
            for (int i = 0; i < 4; ++i) acc[n][i] = 0.0f;
#pragma unroll
        for (int kt = 0; kt < 4; ++kt) {
            u32 kc = (u32)(kt << 5);
            u32 aoff = (kc | aco) ^ swz;
            u32 aH0, aH1, aH2, aH3, aL0, aL1, aL2, aL3;
            LDSM4(aH0, aH1, aH2, aH3, abase + aoff);
            LDSM4(aL0, aL1, aL2, aL3, abase + 8192 + aoff);
            u32 boff = (kc | bco) ^ swz;
#pragma unroll
            for (int np = 0; np < 4; ++np) {
                u32 bb = bbase + np * 2048 + boff;
                u32 h0, h1, h2, h3, l0, l1, l2, l3;
                LDSM4(h0, h1, h2, h3, bb);
                LDSM4(l0, l1, l2, l3, bb + 8192);
                mma16816(acc[2 * np],     aH0, aH1, aH2, aH3, h0, h1);
                mma16816(acc[2 * np + 1], aH0, aH1, aH2, aH3, h2, h3);
                mma16816(acc[2 * np],     aL0, aL1, aL2, aL3, h0, h1);
                mma16816(acc[2 * np + 1], aL0, aL1, aL2, aL3, h2, h3);
                mma16816(acc[2 * np],     aH0, aH1, aH2, aH3, l0, l1);
                mma16816(acc[2 * np + 1], aH0, aH1, aH2, aH3, l2, l3);
            }
        }
        u32 hpA[8], lpA[8], hpB[8], lpB[8];
#pragma unroll
        for (int nt = 0; nt < 8; ++nt) {
            float vA0 = fast_tanh(acc[nt][0] + fmaf(xA, wi2[nt].x, b02[nt].x));
            float vA1 = fast_tanh(acc[nt][1] + fmaf(xA, wi2[nt].y, b02[nt].y));
            float vB0 = fast_tanh(acc[nt][2] + fmaf(xB, wi2[nt].x, b02[nt].x));
            float vB1 = fast_tanh(acc[nt][3] + fmaf(xB, wi2[nt].y, b02[nt].y));
            u32 hA = cvtpack(vA1, vA0), hB = cvtpack(vB1, vB0);
            float aLo = __uint_as_float(hA << 16);
            float aHi = __uint_as_float(hA & 0xFFFF0000u);
            float bLo = __uint_as_float(hB << 16);
            float bHi = __uint_as_float(hB & 0xFFFF0000u);
            hpA[nt] = hA; hpB[nt] = hB;
            lpA[nt] = cvtpack(vA1 - aHi, vA0 - aLo);
            lpB[nt] = cvtpack(vB1 - bHi, vB0 - bLo);
        }
        __syncwarp();
#pragma unroll
        for (int nt = 0; nt < 8; ++nt) {
            asm volatile("st.shared.b32 [%0], %1;" :: "r"(stA[nt]), "r"(hpA[nt]));
            asm volatile("st.shared.b32 [%0], %1;" :: "r"(stB[nt]), "r"(hpB[nt]));
            asm volatile("st.shared.b32 [%0], %1;" :: "r"(stA[nt] + 8192), "r"(lpA[nt]));
            asm volatile("st.shared.b32 [%0], %1;" :: "r"(stB[nt] + 8192), "r"(lpB[nt]));
        }
        __syncwarp();

        // ================= layer 1 =================
#pragma unroll
        for (int n = 0; n < 8; ++n)
#pragma unroll
            for (int i = 0; i < 4; ++i) acc[n][i] = 0.0f;
#pragma unroll
        for (int kt = 0; kt < 4; ++kt) {
            u32 kc = (u32)(kt << 5);
            u32 aoff = (kc | aco) ^ swz;
            u32 p0, p1, p2, p3, q0, q1, q2, q3;
            u32 r0, r1, r2, r3, s0, s1, s2, s3;
            LDSM4(p0, p1, p2, p3, abase + aoff);
            LDSM4(q0, q1, q2, q3, abase + 8192 + aoff);
            LDSM4(r0, r1, r2, r3, abase + 16384 + aoff);
            LDSM4(s0, s1, s2, s3, abase + 24576 + aoff);
            u32 boff = (kc | bco) ^ swz;
#pragma unroll
            for (int np = 0; np < 4; ++np) {
                u32 bb = bbase + np * 2048 + boff;
                u32 ih0, ih1, ih2, ih3, il0, il1, il2, il3;
                u32 hh0, hh1, hh2, hh3, hl0, hl1, hl2, hl3;
                LDSM4(ih0, ih1, ih2, ih3, bb + 16384);
                LDSM4(il0, il1, il2, il3, bb + 24576);
                LDSM4(hh0, hh1, hh2, hh3, bb + 32768);
                LDSM4(hl0, hl1, hl2, hl3, bb + 40960);
                mma16816(acc[2 * np],     p0, p1, p2, p3, ih0, ih1);
                mma16816(acc[2 * np + 1], p0, p1, p2, p3, ih2, ih3);
                mma16816(acc[2 * np],     q0, q1, q2, q3, ih0, ih1);
                mma16816(acc[2 * np + 1], q0, q1, q2, q3, ih2, ih3);
                mma16816(acc[2 * np],     p0, p1, p2, p3, il0, il1);
                mma16816(acc[2 * np + 1], p0, p1, p2, p3, il2, il3);
                mma16816(acc[2 * np],     r0, r1, r2, r3, hh0, hh1);
                mma16816(acc[2 * np + 1], r0, r1, r2, r3, hh2, hh3);
                mma16816(acc[2 * np],     s0, s1, s2, s3, hh0, hh1);
                mma16816(acc[2 * np + 1], s0, s1, s2, s3, hh2, hh3);
                mma16816(acc[2 * np],     r0, r1, r2, r3, hl0, hl1);
                mma16816(acc[2 * np + 1], r0, r1, r2, r3, hl2, hl3);
            }
        }
        float ypA = 0.0f, ypB = 0.0f;
#pragma unroll
        for (int nt = 0; nt < 8; ++nt) {
            float vA0 = fast_tanh(acc[nt][0] + b12[nt].x);
            float vA1 = fast_tanh(acc[nt][1] + b12[nt].y);
            float vB0 = fast_tanh(acc[nt][2] + b12[nt].x);
            float vB1 = fast_tanh(acc[nt][3] + b12[nt].y);
            ypA = fmaf(vA0, wo2[nt].x, ypA); ypA = fmaf(vA1, wo2[nt].y, ypA);
            ypB = fmaf(vB0, wo2[nt].x, ypB); ypB = fmaf(vB1, wo2[nt].y, ypB);
            u32 hA = cvtpack(vA1, vA0), hB = cvtpack(vB1, vB0);
            float aLo = __uint_as_float(hA << 16);
            float aHi = __uint_as_float(hA & 0xFFFF0000u);
            float bLo = __uint_as_float(hB << 16);
            float bHi = __uint_as_float(hB & 0xFFFF0000u);
            hpA[nt] = hA; hpB[nt] = hB;
            lpA[nt] = cvtpack(vA1 - aHi, vA0 - aLo);
            lpB[nt] = cvtpack(vB1 - bHi, vB0 - bLo);
        }
        __syncwarp();
#pragma unroll
        for (int nt = 0; nt < 8; ++nt) {
            asm volatile("st.shared.b32 [%0], %1;" :: "r"(stA[nt] + 16384), "r"(hpA[nt]));
            asm volatile("st.shared.b32 [%0], %1;" :: "r"(stB[nt] + 16384), "r"(hpB[nt]));
            asm volatile("st.shared.b32 [%0], %1;" :: "r"(stA[nt] + 24576), "r"(lpA[nt]));
            asm volatile("st.shared.b32 [%0], %1;" :: "r"(stB[nt] + 24576), "r"(lpB[nt]));
        }
        ypA += __shfl_xor_sync(0xFFFFFFFF, ypA, 1);
        ypA += __shfl_xor_sync(0xFFFFFFFF, ypA, 2);
        ypB += __shfl_xor_sync(0xFFFFFFFF, ypB, 1);
        ypB += __shfl_xor_sync(0xFFFFFFFF, ypB, 2);
        if (tg == 0) {
            outy[t]          = ypA + bo;
            outy[8 * TT + t] = ypB + bo;
        }
        __syncwarp();
    }
    __syncthreads();

    // ---- h_final from hi+lo ----
    const int BT = BB * TT;
    for (int idx = tid; idx < MROWS * 64; idx += THREADS) {
        int r = idx >> 6, k = idx & 63;
        int sw = r * 128 + ((k * 2) ^ ((r & 7) << 4));
        float h0 = __bfloat162float(*(__nv_bfloat16*)(smem + OFF_H + sw)) +
                   __bfloat162float(*(__nv_bfloat16*)(smem + OFF_H + 8192 + sw));
        float h1 = __bfloat162float(*(__nv_bfloat16*)(smem + OFF_H + 16384 + sw)) +
                   __bfloat162float(*(__nv_bfloat16*)(smem + OFF_H + 24576 + sw));
        out[BT + (row0 + r) * 64 + k]           = h0;
        out[BT + BB * 64 + (row0 + r) * 64 + k] = h1;
    }
}

extern "C" void kernel_launch(void* const* d_in, const int* in_sizes, int n_in,
                              void* d_out, int out_size) {
    (void)in_sizes; (void)n_in; (void)out_size;
    const float* x    = (const float*)d_in[0];
    const float* hs   = (const float*)d_in[1];
    const float* Wih0 = (const float*)d_in[2];
    const float* Whh0 = (const float*)d_in[3];
    const float* bih0 = (const float*)d_in[4];
    const float* bhh0 = (const float*)d_in[5];
    const float* Wih1 = (const float*)d_in[6];
    const float* Whh1 = (const float*)d_in[7];
    const float* bih1 = (const float*)d_in[8];
    const float* bhh1 = (const float*)d_in[9];
    const float* Wout = (const float*)d_in[10];
    const float* bout = (const float*)d_in[11];
    float* out = (float*)d_out;

    cudaFuncSetAttribute(rnn_kernel, cudaFuncAttributeMaxDynamicSharedMemorySize,
                         SMEM_BYTES);
    rnn_kernel<<<BB / MROWS, THREADS, SMEM_BYTES>>>(
        x, hs, Wih0, Whh0, bih0, bhh0, Wih1, Whh1, bih1, bhh1, Wout, bout, out);
}